// round 7
// baseline (speedup 1.0000x reference)
#include <cuda_runtime.h>
#include <cstdint>

#define NBATCH 32
#define C 192
#define C3 576
#define T 256
#define V 25
#define TV 6400
#define S 3
#define MID 64

// Scratch (device globals). All tensor-core operands stored pre-rounded to tf32.
__device__ float g_xT [NBATCH * C  * TV];   // [n][c][v][t] (tf32)
__device__ float g_qkv[NBATCH * C3 * TV];   // [n][d][v][t] (tf32)
__device__ float g_att[NBATCH * S * T * T]; // [n*s][q][t]  (tf32)
__device__ float g_y  [NBATCH * C  * TV];   // [n][ch][t][v] (tf32)
__device__ float g_win[C3 * C];             // tf32 weights
__device__ float g_wff[C * C];

__device__ __forceinline__ uint32_t f2tf(float f) {
    uint32_t r; asm("cvt.rna.tf32.f32 %0, %1;" : "=r"(r) : "f"(f)); return r;
}
__device__ __forceinline__ float rnd(float f) { return __uint_as_float(f2tf(f)); }
__device__ __forceinline__ void mma8(float* d, const uint32_t* a, const uint32_t* b) {
    asm volatile("mma.sync.aligned.m16n8k8.row.col.f32.tf32.tf32.f32 "
        "{%0,%1,%2,%3}, {%4,%5,%6,%7}, {%8,%9}, {%0,%1,%2,%3};"
        : "+f"(d[0]), "+f"(d[1]), "+f"(d[2]), "+f"(d[3])
        : "r"(a[0]), "r"(a[1]), "r"(a[2]), "r"(a[3]), "r"(b[0]), "r"(b[1]));
}
__device__ __forceinline__ void cpa16(void* s, const void* g) {
    uint32_t sa = (uint32_t)__cvta_generic_to_shared(s);
    asm volatile("cp.async.cg.shared.global [%0], [%1], 16;" :: "r"(sa), "l"(g));
}
__device__ __forceinline__ void cpcommit() { asm volatile("cp.async.commit_group;"); }
template <int N> __device__ __forceinline__ void cpwait() {
    asm volatile("cp.async.wait_group %0;" :: "n"(N));
}
__device__ __forceinline__ uint32_t LDU(const float* p) { return __float_as_uint(*p); }

// 3-way unrolled pipeline driver: load/compute always called with LITERAL buf.
#define PIPE3(NIT, BK, LOADF, COMPF)                                   \
    {                                                                  \
        LOADF(0, 0); cpcommit();                                       \
        LOADF(1, (BK)); cpcommit();                                    \
        int kk_ = 2 * (BK);                                            \
        int rem_ = (NIT);                                              \
        for (;;) {                                                     \
            cpwait<1>(); __syncthreads();                              \
            if (rem_ > 2) { LOADF(2, kk_); kk_ += (BK); }              \
            COMPF(0); cpcommit();                                      \
            if (--rem_ == 0) break;                                    \
            cpwait<1>(); __syncthreads();                              \
            if (rem_ > 2) { LOADF(0, kk_); kk_ += (BK); }              \
            COMPF(1); cpcommit();                                      \
            if (--rem_ == 0) break;                                    \
            cpwait<1>(); __syncthreads();                              \
            if (rem_ > 2) { LOADF(1, kk_); kk_ += (BK); }              \
            COMPF(2); cpcommit();                                      \
            if (--rem_ == 0) break;                                    \
        }                                                              \
    }

// ---------------------------------------------------------------------------
__global__ __launch_bounds__(256) void k_prep(const float* __restrict__ w_in,
                                              const float* __restrict__ w_ff) {
    int i = blockIdx.x * 256 + threadIdx.x;
    if (i < C3 * C) g_win[i] = rnd(w_in[i]);
    if (i < C * C)  g_wff[i] = rnd(w_ff[i]);
}

// x[n][c][t][v] -> xT[n][c][v][t] (tf32)
__global__ __launch_bounds__(256) void k_tr(const float* __restrict__ x) {
    __shared__ float sm[TV];
    size_t base = (size_t)blockIdx.x * TV;
    const int tid = threadIdx.x;
#pragma unroll
    for (int j = 0; j < 25; j++) sm[tid + j * 256] = x[base + tid + j * 256];
    __syncthreads();
#pragma unroll
    for (int j = 0; j < 25; j++) {
        int o = tid + j * 256;
        int t = o & 255, v = o >> 8;
        g_xT[base + o] = rnd(sm[t * 25 + v]);
    }
}

// ---------------------------------------------------------------------------
// QKV: block 64x256, warp 32x64, 3-stage pipeline. K=192, NIT=12.
// ---------------------------------------------------------------------------
__global__ __launch_bounds__(256) void k_qkv(const float* __restrict__ bias) {
    __shared__ __align__(16) float As[3][64 * 20];
    __shared__ __align__(16) float Bs[3][16 * 264];
    const int bz = blockIdx.z, m0 = blockIdx.y * 64, n0 = blockIdx.x * 256;
    const int tid = threadIdx.x, lane = tid & 31, wid = tid >> 5;
    const int g = lane >> 2, tg = lane & 3;
    const int wm = (wid >> 2) * 32, wn = (wid & 3) * 64;
    const float* Bg = g_xT + (size_t)bz * C * TV + n0;
    const int am = tid >> 2, ak = (tid & 3) * 4;
    const int bk = tid >> 6, bn = (tid & 63) * 4;

    float acc[2][8][4] = {};

#define QKV_LOAD(BUF, KK)                                                          \
    {                                                                              \
        cpa16(&As[BUF][am * 20 + ak], g_win + (m0 + am) * C + (KK) + ak);          \
        _Pragma("unroll")                                                          \
        for (int r = 0; r < 16; r += 4)                                            \
            cpa16(&Bs[BUF][(bk + r) * 264 + bn], Bg + (size_t)((KK) + bk + r) * TV + bn); \
    }
#define QKV_COMP(BUF)                                                              \
    {                                                                              \
        _Pragma("unroll")                                                          \
        for (int ks = 0; ks < 2; ks++) {                                           \
            uint32_t a[2][4], b[8][2];                                             \
            _Pragma("unroll")                                                      \
            for (int mi = 0; mi < 2; mi++) {                                       \
                const float* Ap = &As[BUF][(wm + mi * 16) * 20 + ks * 8];          \
                a[mi][0] = LDU(Ap + g * 20 + tg);                                  \
                a[mi][1] = LDU(Ap + (g + 8) * 20 + tg);                            \
                a[mi][2] = LDU(Ap + g * 20 + tg + 4);                              \
                a[mi][3] = LDU(Ap + (g + 8) * 20 + tg + 4);                        \
            }                                                                      \
            _Pragma("unroll")                                                      \
            for (int ni = 0; ni < 8; ni++) {                                       \
                const float* Bp = &Bs[BUF][ks * 8 * 264 + wn + ni * 8 + g];        \
                b[ni][0] = LDU(Bp + tg * 264);                                     \
                b[ni][1] = LDU(Bp + (tg + 4) * 264);                               \
            }                                                                      \
            _Pragma("unroll")                                                      \
            for (int mi = 0; mi < 2; mi++)                                         \
                _Pragma("unroll")                                                  \
                for (int ni = 0; ni < 8; ni++) mma8(acc[mi][ni], a[mi], b[ni]);    \
        }                                                                          \
    }

    PIPE3(12, 16, QKV_LOAD, QKV_COMP)

#pragma unroll
    for (int mi = 0; mi < 2; mi++) {
        int r0 = m0 + wm + mi * 16 + g;
        float b0 = bias[r0], b1 = bias[r0 + 8];
#pragma unroll
        for (int ni = 0; ni < 8; ni++) {
            int col = n0 + wn + ni * 8 + 2 * tg;
            float2 v0 = make_float2(rnd(acc[mi][ni][0] + b0), rnd(acc[mi][ni][1] + b0));
            float2 v1 = make_float2(rnd(acc[mi][ni][2] + b1), rnd(acc[mi][ni][3] + b1));
            *(float2*)&g_qkv[(size_t)(bz * C3 + r0) * TV + col] = v0;
            *(float2*)&g_qkv[(size_t)(bz * C3 + r0 + 8) * TV + col] = v1;
        }
    }
}

// ---------------------------------------------------------------------------
// Scores: att[ns][q][t] = tanh(sum_k K[k][q]*Q[k][t]/1600), K=1600, NIT=100.
// Block 64x128, warp 32x32.
// ---------------------------------------------------------------------------
__global__ __launch_bounds__(256) void k_att() {
    __shared__ __align__(16) float As[3][16 * 72];
    __shared__ __align__(16) float Bs[3][16 * 136];
    const int bz = blockIdx.z;
    const int nb = bz / 3, s = bz - nb * 3;
    const int m0 = blockIdx.y * 64, n0 = blockIdx.x * 128;
    const int tid = threadIdx.x, lane = tid & 31, wid = tid >> 5;
    const int g = lane >> 2, tg = lane & 3;
    const int wm = (wid >> 2) * 32, wn = (wid & 3) * 32;
    const float* Ag = g_qkv + ((size_t)nb * C3 + C + s * MID) * TV + m0;  // K [k][m]
    const float* Bg = g_qkv + ((size_t)nb * C3 + s * MID) * TV + n0;      // Q [k][n]
    const int ar = tid >> 4, ac = (tid & 15) * 4;
    const int br = tid >> 5, bc = (tid & 31) * 4;

    float acc[2][4][4] = {};

#define ATT_LOAD(BUF, KK)                                                          \
    {                                                                              \
        cpa16(&As[BUF][ar * 72 + ac], Ag + (size_t)((KK) + ar) * T + ac);          \
        cpa16(&Bs[BUF][br * 136 + bc], Bg + (size_t)((KK) + br) * T + bc);         \
        cpa16(&Bs[BUF][(br + 8) * 136 + bc], Bg + (size_t)((KK) + br + 8) * T + bc); \
    }
#define ATT_COMP(BUF)                                                              \
    {                                                                              \
        _Pragma("unroll")                                                          \
        for (int ks = 0; ks < 2; ks++) {                                           \
            uint32_t a[2][4], b[4][2];                                             \
            _Pragma("unroll")                                                      \
            for (int mi = 0; mi < 2; mi++) {                                       \
                const float* Ap = &As[BUF][ks * 8 * 72 + wm + mi * 16];            \
                a[mi][0] = LDU(Ap + tg * 72 + g);                                  \
                a[mi][1] = LDU(Ap + tg * 72 + g + 8);                              \
                a[mi][2] = LDU(Ap + (tg + 4) * 72 + g);                            \
                a[mi][3] = LDU(Ap + (tg + 4) * 72 + g + 8);                        \
            }                                                                      \
            _Pragma("unroll")                                                      \
            for (int ni = 0; ni < 4; ni++) {                                       \
                const float* Bp = &Bs[BUF][ks * 8 * 136 + wn + ni * 8 + g];        \
                b[ni][0] = LDU(Bp + tg * 136);                                     \
                b[ni][1] = LDU(Bp + (tg + 4) * 136);                               \
            }                                                                      \
            _Pragma("unroll")                                                      \
            for (int mi = 0; mi < 2; mi++)                                         \
                _Pragma("unroll")                                                  \
                for (int ni = 0; ni < 4; ni++) mma8(acc[mi][ni], a[mi], b[ni]);    \
        }                                                                          \
    }

    PIPE3(100, 16, ATT_LOAD, ATT_COMP)

    const float scl = 1.f / 1600.f;
#pragma unroll
    for (int mi = 0; mi < 2; mi++) {
        int q0r = m0 + wm + mi * 16 + g;
#pragma unroll
        for (int ni = 0; ni < 4; ni++) {
            int col = n0 + wn + ni * 8 + 2 * tg;
            float2 v0 = make_float2(rnd(tanhf(acc[mi][ni][0] * scl)), rnd(tanhf(acc[mi][ni][1] * scl)));
            float2 v1 = make_float2(rnd(tanhf(acc[mi][ni][2] * scl)), rnd(tanhf(acc[mi][ni][3] * scl)));
            *(float2*)&g_att[((size_t)bz * T + q0r) * T + col] = v0;
            *(float2*)&g_att[((size_t)bz * T + q0r + 8) * T + col] = v1;
        }
    }
}

// ---------------------------------------------------------------------------
// att.V: block 64x128, warp 32x32, K=256, NIT=16. Epilogue transpose via smem.
// ---------------------------------------------------------------------------
__global__ __launch_bounds__(256) void k_av() {
    __shared__ __align__(16) float SM[3 * 1280 + 3 * 2176];
    const int bz = blockIdx.z;
    const int nb = bz / 3, s = bz - nb * 3;
    const int m0 = blockIdx.y * 64, n0 = blockIdx.x * 128;
    const int tid = threadIdx.x, lane = tid & 31, wid = tid >> 5;
    const int g = lane >> 2, tg = lane & 3;
    const int wm = (wid >> 2) * 32, wn = (wid & 3) * 32;
    const float* Ag = g_qkv + ((size_t)nb * C3 + 2 * C + s * MID) * TV;  // V [m][k]
    const float* Bg = g_att + (size_t)bz * T * T + n0;
    const int am = tid >> 2, ak = (tid & 3) * 4;
    const int bk = tid >> 5, bn = (tid & 31) * 4;
    float* As0 = SM;
    float* Bs0 = SM + 3 * 1280;

    float acc[2][4][4] = {};

#define AV_LOAD(BUF, KK)                                                           \
    {                                                                              \
        cpa16(&As0[(BUF) * 1280 + am * 20 + ak], Ag + (size_t)(m0 + am) * T + (KK) + ak); \
        cpa16(&Bs0[(BUF) * 2176 + bk * 136 + bn], Bg + (size_t)((KK) + bk) * T + bn);     \
        cpa16(&Bs0[(BUF) * 2176 + (bk + 8) * 136 + bn], Bg + (size_t)((KK) + bk + 8) * T + bn); \
    }
#define AV_COMP(BUF)                                                               \
    {                                                                              \
        _Pragma("unroll")                                                          \
        for (int ks = 0; ks < 2; ks++) {                                           \
            uint32_t a[2][4], b[4][2];                                             \
            _Pragma("unroll")                                                      \
            for (int mi = 0; mi < 2; mi++) {                                       \
                const float* Ap = &As0[(BUF) * 1280 + (wm + mi * 16) * 20 + ks * 8]; \
                a[mi][0] = LDU(Ap + g * 20 + tg);                                  \
                a[mi][1] = LDU(Ap + (g + 8) * 20 + tg);                            \
                a[mi][2] = LDU(Ap + g * 20 + tg + 4);                              \
                a[mi][3] = LDU(Ap + (g + 8) * 20 + tg + 4);                        \
            }                                                                      \
            _Pragma("unroll")                                                      \
            for (int ni = 0; ni < 4; ni++) {                                       \
                const float* Bp = &Bs0[(BUF) * 2176 + ks * 8 * 136 + wn + ni * 8 + g]; \
                b[ni][0] = LDU(Bp + tg * 136);                                     \
                b[ni][1] = LDU(Bp + (tg + 4) * 136);                               \
            }                                                                      \
            _Pragma("unroll")                                                      \
            for (int mi = 0; mi < 2; mi++)                                         \
                _Pragma("unroll")                                                  \
                for (int ni = 0; ni < 4; ni++) mma8(acc[mi][ni], a[mi], b[ni]);    \
        }                                                                          \
    }

    PIPE3(16, 16, AV_LOAD, AV_COMP)

    __syncthreads();
    // stage 64x128 tile in smem (pitch 129), write y coalesced along v (tf32)
    float* Ys = SM;
#pragma unroll
    for (int mi = 0; mi < 2; mi++) {
        int r0 = wm + mi * 16 + g;
#pragma unroll
        for (int ni = 0; ni < 4; ni++) {
            int col = wn + ni * 8 + 2 * tg;
            Ys[r0 * 129 + col]           = acc[mi][ni][0];
            Ys[r0 * 129 + col + 1]       = acc[mi][ni][1];
            Ys[(r0 + 8) * 129 + col]     = acc[mi][ni][2];
            Ys[(r0 + 8) * 129 + col + 1] = acc[mi][ni][3];
        }
    }
    __syncthreads();
    const int chbase = nb * C + s * MID;
#pragma unroll
    for (int it = 0; it < 32; ++it) {
        int e = tid + it * 256;
        int m = e & 63, tcol = e >> 6;
        int mg = m0 + m;
        int c = mg / 25, v = mg - c * 25;
        g_y[((size_t)(chbase + c) * T + n0 + tcol) * V + v] = rnd(Ys[m * 129 + tcol]);
    }
}

// ---------------------------------------------------------------------------
// FF + BN + residual + LeakyReLU. Block 64x256, warp 32x64. K=192, NIT=12.
// ---------------------------------------------------------------------------
__global__ __launch_bounds__(256) void k_ff(const float* __restrict__ x,
                                            const float* __restrict__ bias,
                                            const float* __restrict__ gamma,
                                            const float* __restrict__ beta,
                                            const float* __restrict__ mean,
                                            const float* __restrict__ var,
                                            float* __restrict__ out) {
    __shared__ __align__(16) float As[3][64 * 20];
    __shared__ __align__(16) float Bs[3][16 * 264];
    const int bz = blockIdx.z, m0 = blockIdx.y * 64, n0 = blockIdx.x * 256;
    const int tid = threadIdx.x, lane = tid & 31, wid = tid >> 5;
    const int g = lane >> 2, tg = lane & 3;
    const int wm = (wid >> 2) * 32, wn = (wid & 3) * 64;
    const float* Bg = g_y + (size_t)bz * C * TV + n0;
    const int am = tid >> 2, ak = (tid & 3) * 4;
    const int bk = tid >> 6, bn = (tid & 63) * 4;

    float acc[2][8][4] = {};

#define FF_LOAD(BUF, KK)                                                           \
    {                                                                              \
        cpa16(&As[BUF][am * 20 + ak], g_wff + (m0 + am) * C + (KK) + ak);          \
        _Pragma("unroll")                                                          \
        for (int r = 0; r < 16; r += 4)                                            \
            cpa16(&Bs[BUF][(bk + r) * 264 + bn], Bg + (size_t)((KK) + bk + r) * TV + bn); \
    }

    PIPE3(12, 16, FF_LOAD, QKV_COMP)

#pragma unroll
    for (int mi = 0; mi < 2; mi++) {
        int r0 = m0 + wm + mi * 16 + g;
        int r1 = r0 + 8;
        float sc0 = gamma[r0] * rsqrtf(var[r0] + 1e-5f);
        float sh0 = beta[r0] - mean[r0] * sc0;
        float bb0 = bias[r0];
        float sc1 = gamma[r1] * rsqrtf(var[r1] + 1e-5f);
        float sh1 = beta[r1] - mean[r1] * sc1;
        float bb1 = bias[r1];
#pragma unroll
        for (int ni = 0; ni < 8; ni++) {
            int col = n0 + wn + ni * 8 + 2 * tg;
            size_t i0 = (size_t)(bz * C + r0) * TV + col;
            size_t i1 = (size_t)(bz * C + r1) * TV + col;
            float2 x0 = *(const float2*)&x[i0];
            float2 x1 = *(const float2*)&x[i1];
            float z, o0x, o0y, o1x, o1y;
            z = x0.x + (acc[mi][ni][0] + bb0) * sc0 + sh0; o0x = z >= 0.f ? z : 0.1f * z;
            z = x0.y + (acc[mi][ni][1] + bb0) * sc0 + sh0; o0y = z >= 0.f ? z : 0.1f * z;
            z = x1.x + (acc[mi][ni][2] + bb1) * sc1 + sh1; o1x = z >= 0.f ? z : 0.1f * z;
            z = x1.y + (acc[mi][ni][3] + bb1) * sc1 + sh1; o1y = z >= 0.f ? z : 0.1f * z;
            *(float2*)&out[i0] = make_float2(o0x, o0y);
            *(float2*)&out[i1] = make_float2(o1x, o1y);
        }
    }
}

extern "C" void kernel_launch(void* const* d_in, const int* in_sizes, int n_in,
                              void* d_out, int out_size) {
    const float* x     = (const float*)d_in[0];
    const float* w_in  = (const float*)d_in[1];
    const float* b_in  = (const float*)d_in[2];
    const float* w_ff  = (const float*)d_in[3];
    const float* b_ff  = (const float*)d_in[4];
    const float* gamma = (const float*)d_in[5];
    const float* beta  = (const float*)d_in[6];
    const float* mean  = (const float*)d_in[7];
    const float* var   = (const float*)d_in[8];
    float* out = (float*)d_out;

    k_prep<<<432, 256>>>(w_in, w_ff);
    k_tr <<<NBATCH * C, 256>>>(x);
    k_qkv<<<dim3(25, 9, 32), 256>>>(b_in);
    k_att<<<dim3(2, 4, 96), 256>>>();
    k_av <<<dim3(2, 25, 96), 256>>>();
    k_ff <<<dim3(25, 3, 32), 256>>>(x, b_ff, gamma, beta, mean, var, out);
}

// round 8
// speedup vs baseline: 2.1835x; 2.1835x over previous
#include <cuda_runtime.h>
#include <cuda_fp16.h>
#include <cstdint>

#define NBATCH 32
#define C 192
#define C3 576
#define T 256
#define V 25
#define TV 6400
#define S 3
#define MID 64

// fp16 scratch (device globals)
__device__ __half g_xTh [NBATCH * C  * TV];   // [n][c][v][t]
__device__ __half g_qkvh[NBATCH * C3 * TV];   // [n][d][v][t]
__device__ __half g_atth[NBATCH * S * T * T]; // [ns][q][t]
__device__ __half g_yh  [NBATCH * C  * TV];   // [n][ch][t][v]
__device__ __half g_winh[C3 * C];
__device__ __half g_wffh[C * C];

__device__ __forceinline__ void ldsm4(uint32_t& r0, uint32_t& r1, uint32_t& r2, uint32_t& r3, uint32_t a) {
    asm volatile("ldmatrix.sync.aligned.m8n8.x4.shared.b16 {%0,%1,%2,%3}, [%4];"
        : "=r"(r0), "=r"(r1), "=r"(r2), "=r"(r3) : "r"(a));
}
__device__ __forceinline__ void ldsm4t(uint32_t& r0, uint32_t& r1, uint32_t& r2, uint32_t& r3, uint32_t a) {
    asm volatile("ldmatrix.sync.aligned.m8n8.x4.trans.shared.b16 {%0,%1,%2,%3}, [%4];"
        : "=r"(r0), "=r"(r1), "=r"(r2), "=r"(r3) : "r"(a));
}
__device__ __forceinline__ void mma16(float* d, const uint32_t* a, const uint32_t* b) {
    asm volatile("mma.sync.aligned.m16n8k16.row.col.f32.f16.f16.f32 "
        "{%0,%1,%2,%3}, {%4,%5,%6,%7}, {%8,%9}, {%0,%1,%2,%3};"
        : "+f"(d[0]), "+f"(d[1]), "+f"(d[2]), "+f"(d[3])
        : "r"(a[0]), "r"(a[1]), "r"(a[2]), "r"(a[3]), "r"(b[0]), "r"(b[1]));
}
__device__ __forceinline__ void cpa16s(uint32_t s, const void* g) {
    asm volatile("cp.async.cg.shared.global [%0], [%1], 16;" :: "r"(s), "l"(g));
}
__device__ __forceinline__ void cpcommit() { asm volatile("cp.async.commit_group;"); }
template <int N> __device__ __forceinline__ void cpwait() {
    asm volatile("cp.async.wait_group %0;" :: "n"(N));
}
#define ROT3(a, b, c) { uint32_t t_ = a; a = b; b = c; c = t_; }

// ---------------------------------------------------------------------------
__global__ __launch_bounds__(256) void k_prep(const float* __restrict__ w_in,
                                              const float* __restrict__ w_ff) {
    int i = blockIdx.x * 256 + threadIdx.x;
    if (i < C3 * C) g_winh[i] = __float2half_rn(w_in[i]);
    if (i < C * C)  g_wffh[i] = __float2half_rn(w_ff[i]);
}

// x[n][c][t][v] fp32 -> xT[n][c][v][t] fp16
__global__ __launch_bounds__(256) void k_tr(const float* __restrict__ x) {
    __shared__ float sm[TV];
    size_t base = (size_t)blockIdx.x * TV;
    const int tid = threadIdx.x;
#pragma unroll
    for (int j = 0; j < 25; j++) sm[tid + j * 256] = x[base + tid + j * 256];
    __syncthreads();
#pragma unroll
    for (int j = 0; j < 25; j++) {
        int o = tid + j * 256;
        int t = o & 255, v = o >> 8;
        g_xTh[base + o] = __float2half_rn(sm[t * 25 + v]);
    }
}

// ---------------------------------------------------------------------------
// QKV: qkv[d][(v,t)] = w*xT + b.  M=576 N=6400 K=192. Block 64x256, warp 32x64.
// BK=32, NIT=6. A [m][k] pitch 40 (ldsm), B [k][n] pitch 264 (ldsm.trans).
// ---------------------------------------------------------------------------
__global__ __launch_bounds__(256) void k_qkv(const float* __restrict__ bias) {
    constexpr int PA = 40, PB = 264;
    constexpr int ABH = 64 * PA, BBH = 32 * PB;            // halves per buffer
    __shared__ __align__(16) __half sh[3 * (ABH + BBH)];
    const int bz = blockIdx.z, m0 = blockIdx.y * 64, n0 = blockIdx.x * 256;
    const int tid = threadIdx.x, lane = tid & 31, wid = tid >> 5;
    const int g = lane >> 2, tg = lane & 3;
    const int wm = (wid >> 2) * 32, wn = (wid & 3) * 64;
    const __half* Bg = g_xTh + (size_t)bz * C * TV + n0;
    uint32_t sb = (uint32_t)__cvta_generic_to_shared(sh);
    uint32_t A0 = sb, B0 = sb + 3 * ABH * 2;

    // fragment lane offsets (bytes)
    uint32_t aLO = (((lane & 15)) * PA + (lane >> 4) * 8) * 2;
    uint32_t aF[2][2];
#pragma unroll
    for (int mi = 0; mi < 2; mi++)
#pragma unroll
        for (int ks = 0; ks < 2; ks++)
            aF[mi][ks] = aLO + ((wm + mi * 16) * PA + ks * 16) * 2;
    uint32_t bLO = (((lane & 7) + ((lane >> 3) & 1) * 8) * PB + (lane >> 4) * 8) * 2;
    uint32_t bF[4][2];
#pragma unroll
    for (int j = 0; j < 4; j++)
#pragma unroll
        for (int ks = 0; ks < 2; ks++)
            bF[j][ks] = bLO + (wn + j * 16) * 2 + ks * 16 * PB * 2;

    // producer offsets
    const int arow = tid >> 2, ac8 = (tid & 3) * 8;
    const uint32_t aSt = (arow * PA + ac8) * 2;
    const int brow = tid >> 3, bc0 = (tid & 7) * 32;

    float acc[2][8][4] = {};

    auto LOAD = [&](uint32_t aB, uint32_t bB, int kk) {
        cpa16s(aB + aSt, g_winh + (m0 + arow) * C + kk + ac8);
#pragma unroll
        for (int i = 0; i < 4; i++)
            cpa16s(bB + (brow * PB + bc0 + i * 8) * 2,
                   Bg + (size_t)(kk + brow) * TV + bc0 + i * 8);
    };
    auto COMP = [&](uint32_t aB, uint32_t bB) {
#pragma unroll
        for (int ks = 0; ks < 2; ks++) {
            uint32_t a[2][4], b[8][2];
#pragma unroll
            for (int mi = 0; mi < 2; mi++)
                ldsm4(a[mi][0], a[mi][1], a[mi][2], a[mi][3], aB + aF[mi][ks]);
#pragma unroll
            for (int j = 0; j < 4; j++)
                ldsm4t(b[2 * j][0], b[2 * j][1], b[2 * j + 1][0], b[2 * j + 1][1], bB + bF[j][ks]);
#pragma unroll
            for (int mi = 0; mi < 2; mi++)
#pragma unroll
                for (int ni = 0; ni < 8; ni++) mma16(acc[mi][ni], a[mi], b[ni]);
        }
    };

    uint32_t aC = A0, aN = A0 + ABH * 2, aL = A0 + 2 * ABH * 2;
    uint32_t bC = B0, bN = B0 + BBH * 2, bL = B0 + 2 * BBH * 2;
    LOAD(aC, bC, 0); cpcommit();
    LOAD(aN, bN, 32); cpcommit();
    int kk = 64;
    const int NIT = 6;
#pragma unroll 1
    for (int it = 0; it < NIT; ++it) {
        cpwait<1>(); __syncthreads();
        if (it + 2 < NIT) { LOAD(aL, bL, kk); kk += 32; }
        COMP(aC, bC);
        cpcommit();
        ROT3(aC, aN, aL); ROT3(bC, bN, bL);
    }
#pragma unroll
    for (int mi = 0; mi < 2; mi++) {
        int r0 = m0 + wm + mi * 16 + g;
        float b0 = bias[r0], b1 = bias[r0 + 8];
#pragma unroll
        for (int ni = 0; ni < 8; ni++) {
            int col = n0 + wn + ni * 8 + 2 * tg;
            *(__half2*)&g_qkvh[(size_t)(bz * C3 + r0) * TV + col] =
                __floats2half2_rn(acc[mi][ni][0] + b0, acc[mi][ni][1] + b0);
            *(__half2*)&g_qkvh[(size_t)(bz * C3 + r0 + 8) * TV + col] =
                __floats2half2_rn(acc[mi][ni][2] + b1, acc[mi][ni][3] + b1);
        }
    }
}

// ---------------------------------------------------------------------------
// Scores: att[q][t] = tanh(sum_k K[k][q]*Q[k][t]/1600). K=1600, BK=32, NIT=50.
// Block 64(q)x128(t), warp 32x32. A [k][m] pitch 72 (trans), B [k][n] pitch 136 (trans).
// ---------------------------------------------------------------------------
__global__ __launch_bounds__(256) void k_att() {
    constexpr int PA = 72, PB = 136;
    constexpr int ABH = 32 * PA, BBH = 32 * PB;
    __shared__ __align__(16) __half sh[3 * (ABH + BBH)];
    const int bz = blockIdx.z;
    const int nb = bz / 3, s = bz - nb * 3;
    const int m0 = blockIdx.y * 64, n0 = blockIdx.x * 128;
    const int tid = threadIdx.x, lane = tid & 31, wid = tid >> 5;
    const int g = lane >> 2, tg = lane & 3;
    const int wm = (wid >> 2) * 32, wn = (wid & 3) * 32;
    const __half* Ag = g_qkvh + ((size_t)nb * C3 + C + s * MID) * TV + m0;
    const __half* Bg = g_qkvh + ((size_t)nb * C3 + s * MID) * TV + n0;
    uint32_t sb = (uint32_t)__cvta_generic_to_shared(sh);
    uint32_t A0 = sb, B0 = sb + 3 * ABH * 2;

    // A trans frag offsets: groups (k0,m0)(k0,m8)(k8,m0)(k8,m8)
    uint32_t aLO = (((lane & 7) + (lane >> 4) * 8) * PA + ((lane >> 3) & 1) * 8) * 2;
    uint32_t aF[2][2];
#pragma unroll
    for (int mi = 0; mi < 2; mi++)
#pragma unroll
        for (int ks = 0; ks < 2; ks++)
            aF[mi][ks] = aLO + (wm + mi * 16) * 2 + ks * 16 * PA * 2;
    uint32_t bLO = (((lane & 7) + ((lane >> 3) & 1) * 8) * PB + (lane >> 4) * 8) * 2;
    uint32_t bF[2][2];
#pragma unroll
    for (int j = 0; j < 2; j++)
#pragma unroll
        for (int ks = 0; ks < 2; ks++)
            bF[j][ks] = bLO + (wn + j * 16) * 2 + ks * 16 * PB * 2;

    const int arow = tid >> 3, ac8 = (tid & 7) * 8;
    const uint32_t aSt = (arow * PA + ac8) * 2;
    const int brow = tid >> 4, bc8 = (tid & 15) * 8;

    float acc[2][4][4] = {};

    auto LOAD = [&](uint32_t aB, uint32_t bB, int kk) {
        cpa16s(aB + aSt, Ag + (size_t)(kk + arow) * T + ac8);
        cpa16s(bB + (brow * PB + bc8) * 2, Bg + (size_t)(kk + brow) * T + bc8);
        cpa16s(bB + ((brow + 16) * PB + bc8) * 2, Bg + (size_t)(kk + brow + 16) * T + bc8);
    };
    auto COMP = [&](uint32_t aB, uint32_t bB) {
#pragma unroll
        for (int ks = 0; ks < 2; ks++) {
            uint32_t a[2][4], b[4][2];
#pragma unroll
            for (int mi = 0; mi < 2; mi++)
                ldsm4t(a[mi][0], a[mi][1], a[mi][2], a[mi][3], aB + aF[mi][ks]);
#pragma unroll
            for (int j = 0; j < 2; j++)
                ldsm4t(b[2 * j][0], b[2 * j][1], b[2 * j + 1][0], b[2 * j + 1][1], bB + bF[j][ks]);
#pragma unroll
            for (int mi = 0; mi < 2; mi++)
#pragma unroll
                for (int ni = 0; ni < 4; ni++) mma16(acc[mi][ni], a[mi], b[ni]);
        }
    };

    uint32_t aC = A0, aN = A0 + ABH * 2, aL = A0 + 2 * ABH * 2;
    uint32_t bC = B0, bN = B0 + BBH * 2, bL = B0 + 2 * BBH * 2;
    LOAD(aC, bC, 0); cpcommit();
    LOAD(aN, bN, 32); cpcommit();
    int kk = 64;
    const int NIT = 50;
#pragma unroll 1
    for (int it = 0; it < NIT; ++it) {
        cpwait<1>(); __syncthreads();
        if (it + 2 < NIT) { LOAD(aL, bL, kk); kk += 32; }
        COMP(aC, bC);
        cpcommit();
        ROT3(aC, aN, aL); ROT3(bC, bN, bL);
    }
    const float scl = 1.f / 1600.f;
#pragma unroll
    for (int mi = 0; mi < 2; mi++) {
        int q0r = m0 + wm + mi * 16 + g;
#pragma unroll
        for (int ni = 0; ni < 4; ni++) {
            int col = n0 + wn + ni * 8 + 2 * tg;
            *(__half2*)&g_atth[((size_t)bz * T + q0r) * T + col] =
                __floats2half2_rn(tanhf(acc[mi][ni][0] * scl), tanhf(acc[mi][ni][1] * scl));
            *(__half2*)&g_atth[((size_t)bz * T + q0r + 8) * T + col] =
                __floats2half2_rn(tanhf(acc[mi][ni][2] * scl), tanhf(acc[mi][ni][3] * scl));
        }
    }
}

// ---------------------------------------------------------------------------
// att.V: y[(c,v)][t] = sum_q V[(c,v)][q] * att[q][t]. K=256, BK=32, NIT=8.
// Block 64x128, warp 32x32. A [m][k] pitch 40 (ldsm), B [k][n] pitch 136 (trans).
// ---------------------------------------------------------------------------
__global__ __launch_bounds__(256) void k_av() {
    constexpr int PA = 40, PB = 136;
    constexpr int ABH = 64 * PA, BBH = 32 * PB;
    __shared__ __align__(16) __half sh[3 * (ABH + BBH)];
    const int bz = blockIdx.z;
    const int nb = bz / 3, s = bz - nb * 3;
    const int m0 = blockIdx.y * 64, n0 = blockIdx.x * 128;
    const int tid = threadIdx.x, lane = tid & 31, wid = tid >> 5;
    const int g = lane >> 2, tg = lane & 3;
    const int wm = (wid >> 2) * 32, wn = (wid & 3) * 32;
    const __half* Ag = g_qkvh + ((size_t)nb * C3 + 2 * C + s * MID) * TV;
    const __half* Bg = g_atth + (size_t)bz * T * T + n0;
    uint32_t sb = (uint32_t)__cvta_generic_to_shared(sh);
    uint32_t A0 = sb, B0 = sb + 3 * ABH * 2;

    uint32_t aLO = (((lane & 15)) * PA + (lane >> 4) * 8) * 2;
    uint32_t aF[2][2];
#pragma unroll
    for (int mi = 0; mi < 2; mi++)
#pragma unroll
        for (int ks = 0; ks < 2; ks++)
            aF[mi][ks] = aLO + ((wm + mi * 16) * PA + ks * 16) * 2;
    uint32_t bLO = (((lane & 7) + ((lane >> 3) & 1) * 8) * PB + (lane >> 4) * 8) * 2;
    uint32_t bF[2][2];
#pragma unroll
    for (int j = 0; j < 2; j++)
#pragma unroll
        for (int ks = 0; ks < 2; ks++)
            bF[j][ks] = bLO + (wn + j * 16) * 2 + ks * 16 * PB * 2;

    const int arow = tid >> 2, ac8 = (tid & 3) * 8;
    const uint32_t aSt = (arow * PA + ac8) * 2;
    const int brow = tid >> 4, bc8 = (tid & 15) * 8;

    float acc[2][4][4] = {};

    auto LOAD = [&](uint32_t aB, uint32_t bB, int kk) {
        cpa16s(aB + aSt, Ag + (size_t)(m0 + arow) * T + kk + ac8);
        cpa16s(bB + (brow * PB + bc8) * 2, Bg + (size_t)(kk + brow) * T + bc8);
        cpa16s(bB + ((brow + 16) * PB + bc8) * 2, Bg + (size_t)(kk + brow + 16) * T + bc8);
    };
    auto COMP = [&](uint32_t aB, uint32_t bB) {
#pragma unroll
        for (int ks = 0; ks < 2; ks++) {
            uint32_t a[2][4], b[4][2];
#pragma unroll
            for (int mi = 0; mi < 2; mi++)
                ldsm4(a[mi][0], a[mi][1], a[mi][2], a[mi][3], aB + aF[mi][ks]);
#pragma unroll
            for (int j = 0; j < 2; j++)
                ldsm4t(b[2 * j][0], b[2 * j][1], b[2 * j + 1][0], b[2 * j + 1][1], bB + bF[j][ks]);
#pragma unroll
            for (int mi = 0; mi < 2; mi++)
#pragma unroll
                for (int ni = 0; ni < 4; ni++) mma16(acc[mi][ni], a[mi], b[ni]);
        }
    };

    uint32_t aC = A0, aN = A0 + ABH * 2, aL = A0 + 2 * ABH * 2;
    uint32_t bC = B0, bN = B0 + BBH * 2, bL = B0 + 2 * BBH * 2;
    LOAD(aC, bC, 0); cpcommit();
    LOAD(aN, bN, 32); cpcommit();
    int kk = 64;
    const int NIT = 8;
#pragma unroll 1
    for (int it = 0; it < NIT; ++it) {
        cpwait<1>(); __syncthreads();
        if (it + 2 < NIT) { LOAD(aL, bL, kk); kk += 32; }
        COMP(aC, bC);
        cpcommit();
        ROT3(aC, aN, aL); ROT3(bC, bN, bL);
    }
    __syncthreads();
    // stage 64x128 fp32 tile (pitch 129) in smem, write y[ch][t][v] fp16 coalesced-ish
    float* Ys = (float*)sh;
#pragma unroll
    for (int mi = 0; mi < 2; mi++) {
        int r0 = wm + mi * 16 + g;
#pragma unroll
        for (int ni = 0; ni < 4; ni++) {
            int col = wn + ni * 8 + 2 * tg;
            Ys[r0 * 129 + col]           = acc[mi][ni][0];
            Ys[r0 * 129 + col + 1]       = acc[mi][ni][1];
            Ys[(r0 + 8) * 129 + col]     = acc[mi][ni][2];
            Ys[(r0 + 8) * 129 + col + 1] = acc[mi][ni][3];
        }
    }
    __syncthreads();
    const int chbase = nb * C + s * MID;
#pragma unroll
    for (int it = 0; it < 32; ++it) {
        int e = tid + it * 256;
        int m = e & 63, tcol = e >> 6;
        int mg = m0 + m;
        int c = mg / 25, v = mg - c * 25;
        g_yh[((size_t)(chbase + c) * T + n0 + tcol) * V + v] = __float2half_rn(Ys[m * 129 + tcol]);
    }
}

// ---------------------------------------------------------------------------
// FF + BN + residual + LeakyReLU. M=192 N=6400 K=192. Block 64x256, warp 32x64.
// ---------------------------------------------------------------------------
__global__ __launch_bounds__(256) void k_ff(const float* __restrict__ x,
                                            const float* __restrict__ bias,
                                            const float* __restrict__ gamma,
                                            const float* __restrict__ beta,
                                            const float* __restrict__ mean,
                                            const float* __restrict__ var,
                                            float* __restrict__ out) {
    constexpr int PA = 40, PB = 264;
    constexpr int ABH = 64 * PA, BBH = 32 * PB;
    __shared__ __align__(16) __half sh[3 * (ABH + BBH)];
    const int bz = blockIdx.z, m0 = blockIdx.y * 64, n0 = blockIdx.x * 256;
    const int tid = threadIdx.x, lane = tid & 31, wid = tid >> 5;
    const int g = lane >> 2, tg = lane & 3;
    const int wm = (wid >> 2) * 32, wn = (wid & 3) * 64;
    const __half* Bg = g_yh + (size_t)bz * C * TV + n0;
    uint32_t sb = (uint32_t)__cvta_generic_to_shared(sh);
    uint32_t A0 = sb, B0 = sb + 3 * ABH * 2;

    uint32_t aLO = (((lane & 15)) * PA + (lane >> 4) * 8) * 2;
    uint32_t aF[2][2];
#pragma unroll
    for (int mi = 0; mi < 2; mi++)
#pragma unroll
        for (int ks = 0; ks < 2; ks++)
            aF[mi][ks] = aLO + ((wm + mi * 16) * PA + ks * 16) * 2;
    uint32_t bLO = (((lane & 7) + ((lane >> 3) & 1) * 8) * PB + (lane >> 4) * 8) * 2;
    uint32_t bF[4][2];
#pragma unroll
    for (int j = 0; j < 4; j++)
#pragma unroll
        for (int ks = 0; ks < 2; ks++)
            bF[j][ks] = bLO + (wn + j * 16) * 2 + ks * 16 * PB * 2;

    const int arow = tid >> 2, ac8 = (tid & 3) * 8;
    const uint32_t aSt = (arow * PA + ac8) * 2;
    const int brow = tid >> 3, bc0 = (tid & 7) * 32;

    float acc[2][8][4] = {};

    auto LOAD = [&](uint32_t aB, uint32_t bB, int kk) {
        cpa16s(aB + aSt, g_wffh + (m0 + arow) * C + kk + ac8);
#pragma unroll
        for (int i = 0; i < 4; i++)
            cpa16s(bB + (brow * PB + bc0 + i * 8) * 2,
                   Bg + (size_t)(kk + brow) * TV + bc0 + i * 8);
    };
    auto COMP = [&](uint32_t aB, uint32_t bB) {
#pragma unroll
        for (int ks = 0; ks < 2; ks++) {
            uint32_t a[2][4], b[8][2];
#pragma unroll
            for (int mi = 0; mi < 2; mi++)
                ldsm4(a[mi][0], a[mi][1], a[mi][2], a[mi][3], aB + aF[mi][ks]);
#pragma unroll
            for (int j = 0; j < 4; j++)
                ldsm4t(b[2 * j][0], b[2 * j][1], b[2 * j + 1][0], b[2 * j + 1][1], bB + bF[j][ks]);
#pragma unroll
            for (int mi = 0; mi < 2; mi++)
#pragma unroll
                for (int ni = 0; ni < 8; ni++) mma16(acc[mi][ni], a[mi], b[ni]);
        }
    };

    uint32_t aC = A0, aN = A0 + ABH * 2, aL = A0 + 2 * ABH * 2;
    uint32_t bC = B0, bN = B0 + BBH * 2, bL = B0 + 2 * BBH * 2;
    LOAD(aC, bC, 0); cpcommit();
    LOAD(aN, bN, 32); cpcommit();
    int kk = 64;
    const int NIT = 6;
#pragma unroll 1
    for (int it = 0; it < NIT; ++it) {
        cpwait<1>(); __syncthreads();
        if (it + 2 < NIT) { LOAD(aL, bL, kk); kk += 32; }
        COMP(aC, bC);
        cpcommit();
        ROT3(aC, aN, aL); ROT3(bC, bN, bL);
    }
#pragma unroll
    for (int mi = 0; mi < 2; mi++) {
        int r0 = m0 + wm + mi * 16 + g;
        int r1 = r0 + 8;
        float sc0 = gamma[r0] * rsqrtf(var[r0] + 1e-5f);
        float sh0 = beta[r0] - mean[r0] * sc0;
        float bb0 = bias[r0];
        float sc1 = gamma[r1] * rsqrtf(var[r1] + 1e-5f);
        float sh1 = beta[r1] - mean[r1] * sc1;
        float bb1 = bias[r1];
#pragma unroll
        for (int ni = 0; ni < 8; ni++) {
            int col = n0 + wn + ni * 8 + 2 * tg;
            size_t i0 = (size_t)(bz * C + r0) * TV + col;
            size_t i1 = (size_t)(bz * C + r1) * TV + col;
            float2 x0 = *(const float2*)&x[i0];
            float2 x1 = *(const float2*)&x[i1];
            float z, o0x, o0y, o1x, o1y;
            z = x0.x + (acc[mi][ni][0] + bb0) * sc0 + sh0; o0x = z >= 0.f ? z : 0.1f * z;
            z = x0.y + (acc[mi][ni][1] + bb0) * sc0 + sh0; o0y = z >= 0.f ? z : 0.1f * z;
            z = x1.x + (acc[mi][ni][2] + bb1) * sc1 + sh1; o1x = z >= 0.f ? z : 0.1f * z;
            z = x1.y + (acc[mi][ni][3] + bb1) * sc1 + sh1; o1y = z >= 0.f ? z : 0.1f * z;
            *(float2*)&out[i0] = make_float2(o0x, o0y);
            *(float2*)&out[i1] = make_float2(o1x, o1y);
        }
    }
}

extern "C" void kernel_launch(void* const* d_in, const int* in_sizes, int n_in,
                              void* d_out, int out_size) {
    const float* x     = (const float*)d_in[0];
    const float* w_in  = (const float*)d_in[1];
    const float* b_in  = (const float*)d_in[2];
    const float* w_ff  = (const float*)d_in[3];
    const float* b_ff  = (const float*)d_in[4];
    const float* gamma = (const float*)d_in[5];
    const float* beta  = (const float*)d_in[6];
    const float* mean  = (const float*)d_in[7];
    const float* var   = (const float*)d_in[8];
    float* out = (float*)d_out;

    k_prep<<<432, 256>>>(w_in, w_ff);
    k_tr <<<NBATCH * C, 256>>>(x);
    k_qkv<<<dim3(25, 9, 32), 256>>>(b_in);
    k_att<<<dim3(2, 4, 96), 256>>>();
    k_av <<<dim3(2, 25, 96), 256>>>();
    k_ff <<<dim3(25, 3, 32), 256>>>(x, b_ff, gamma, beta, mean, var, out);
}